// round 3
// baseline (speedup 1.0000x reference)
#include <cuda_runtime.h>
#include <cuda_fp16.h>
#include <cuda_bf16.h>

#define N_NODES 100000
#define N_EDGES 1600000
#define TOT (N_EDGES + N_NODES)
#define NB_SCAN ((N_NODES + 1023) / 1024)   // 98

// ---------------- scratch -----------------------------------------------------
__device__ int    g_deg[N_NODES];
__device__ int    g_incl[N_NODES];
__device__ int    g_bsum[128];
__device__ int    g_rowptr[N_NODES + 1];
__device__ int    g_cursor[N_NODES];
__device__ int    g_col[TOT];
__device__ float  g_dinv[N_NODES];
__device__ int    g_is64;

__device__ __half g_G[N_NODES * 64];   // fp16 message buffer A
__device__ __half g_H[N_NODES * 64];   // fp16 message buffer B
__device__ float  g_XT[N_NODES * 64];  // x_temp residual (fp32)

// ---------------- helpers ------------------------------------------------------
__device__ __forceinline__ int load_idx(const void* ei, int pos) {
    if (g_is64) return (int)((const long long*)ei)[pos];
    return ((const int*)ei)[pos];
}

__global__ void k_init(const void* ei) {
    int i = blockIdx.x * blockDim.x + threadIdx.x;
    if (i < N_NODES) g_deg[i] = 1;
    if (i == 0) {
        const long long* p = (const long long*)ei;
        int ok64 = 1;
        #pragma unroll
        for (int j = 0; j < 16; j++) {
            long long v = p[j];
            if (v < 0 || v >= N_NODES) ok64 = 0;
        }
        g_is64 = ok64;
    }
}

__global__ void k_count(const void* ei) {
    int t = blockIdx.x * blockDim.x + threadIdx.x;
    if (t < N_EDGES) atomicAdd(&g_deg[load_idx(ei, N_EDGES + t)], 1);
}

__global__ void k_scan1() {
    __shared__ int s[1024];
    int tid = threadIdx.x;
    int i = blockIdx.x * 1024 + tid;
    int v = (i < N_NODES) ? g_deg[i] : 0;
    s[tid] = v;
    __syncthreads();
    #pragma unroll
    for (int off = 1; off < 1024; off <<= 1) {
        int t = (tid >= off) ? s[tid - off] : 0;
        __syncthreads();
        s[tid] += t;
        __syncthreads();
    }
    if (i < N_NODES) g_incl[i] = s[tid];
    if (tid == 1023) g_bsum[blockIdx.x] = s[1023];
}

__global__ void k_scan2f() {
    __shared__ int sb[128];
    int tid = threadIdx.x;
    if (tid < 128) sb[tid] = (tid < NB_SCAN) ? g_bsum[tid] : 0;
    __syncthreads();
    int boff = 0;
    for (int j = 0; j < (int)blockIdx.x; j++) boff += sb[j];
    int i = blockIdx.x * 1024 + tid;
    if (i < N_NODES) {
        int rp = g_incl[i] - g_deg[i] + boff;
        g_rowptr[i] = rp;
        g_cursor[i] = rp;
        g_dinv[i]   = rsqrtf((float)g_deg[i]);
    }
    if (i == 0) g_rowptr[N_NODES] = TOT;
}

__global__ void k_fill(const void* ei) {
    int t = blockIdx.x * blockDim.x + threadIdx.x;
    if (t < N_EDGES) {
        int s = load_idx(ei, t);
        int d = load_idx(ei, N_EDGES + t);
        g_col[atomicAdd(&g_cursor[d], 1)] = s;
    } else if (t < TOT) {
        int i = t - N_EDGES;
        g_col[atomicAdd(&g_cursor[i], 1)] = i;
    }
}

// ---------------- layer-0 GEMM: G(fp16) = dinv * (x @ W0) ---------------------
__global__ void __launch_bounds__(256) k_gemm0(const float* __restrict__ X,
                                               const float* __restrict__ W,
                                               __half* __restrict__ G) {
    __shared__ float As[32][132];
    __shared__ float Bs[32][64];
    int tid = threadIdx.x;
    int block_row = blockIdx.x * 128;
    int txc = tid & 7;
    int tyr = tid >> 3;

    int lrow = tid >> 1;
    int kh   = (tid & 1) * 16;
    int lkB  = tid >> 3;
    int lcB  = (tid & 7) * 8;

    float acc[4][8];
    #pragma unroll
    for (int i = 0; i < 4; i++)
        #pragma unroll
        for (int j = 0; j < 8; j++) acc[i][j] = 0.f;

    for (int k0 = 0; k0 < 128; k0 += 32) {
        int grow = block_row + lrow;
        #pragma unroll
        for (int j = 0; j < 4; j++) {
            int ko = kh + j * 4;
            float4 v = make_float4(0.f, 0.f, 0.f, 0.f);
            if (grow < N_NODES) v = *(const float4*)&X[(size_t)grow * 128 + k0 + ko];
            As[ko + 0][lrow] = v.x;
            As[ko + 1][lrow] = v.y;
            As[ko + 2][lrow] = v.z;
            As[ko + 3][lrow] = v.w;
        }
        *(float4*)&Bs[lkB][lcB]     = *(const float4*)&W[(size_t)(k0 + lkB) * 64 + lcB];
        *(float4*)&Bs[lkB][lcB + 4] = *(const float4*)&W[(size_t)(k0 + lkB) * 64 + lcB + 4];
        __syncthreads();

        #pragma unroll 8
        for (int kk = 0; kk < 32; kk++) {
            float4 a  = *(const float4*)&As[kk][tyr * 4];
            float4 b0 = *(const float4*)&Bs[kk][txc * 8];
            float4 b1 = *(const float4*)&Bs[kk][txc * 8 + 4];
            float av[4] = {a.x, a.y, a.z, a.w};
            float bv[8] = {b0.x, b0.y, b0.z, b0.w, b1.x, b1.y, b1.z, b1.w};
            #pragma unroll
            for (int i = 0; i < 4; i++)
                #pragma unroll
                for (int j = 0; j < 8; j++)
                    acc[i][j] = fmaf(av[i], bv[j], acc[i][j]);
        }
        __syncthreads();
    }

    #pragma unroll
    for (int i = 0; i < 4; i++) {
        int gr = block_row + tyr * 4 + i;
        if (gr < N_NODES) {
            float di = g_dinv[gr];
            __half2 h[4];
            #pragma unroll
            for (int j = 0; j < 4; j++)
                h[j] = __floats2half2_rn(acc[i][2 * j] * di, acc[i][2 * j + 1] * di);
            *(uint2*)&G[(size_t)gr * 64 + txc * 8] =
                make_uint2(*(unsigned*)&h[0] | 0u, *(unsigned*)&h[1]),
            *(uint2*)&G[(size_t)gr * 64 + txc * 8 + 4] =
                make_uint2(*(unsigned*)&h[2], *(unsigned*)&h[3]);
        }
    }
}

// ---------------- gather helper (fp16 messages, unroll 8) ---------------------
__device__ __forceinline__ void gather_row(const __half* __restrict__ G, int row,
                                           int lane, float& ax, float& ay) {
    int s  = g_rowptr[row];
    int en = g_rowptr[row + 1];
    ax = 0.f; ay = 0.f;
    int e = s;
    for (; e + 8 <= en; e += 8) {
        __half2 h[8];
        #pragma unroll
        for (int j = 0; j < 8; j++) {
            int c = g_col[e + j];
            h[j] = *(const __half2*)&G[(size_t)c * 64 + lane * 2];
        }
        #pragma unroll
        for (int j = 0; j < 8; j++) {
            float2 v = __half22float2(h[j]);
            ax += v.x; ay += v.y;
        }
    }
    for (; e < en; ++e) {
        int c = g_col[e];
        float2 v = __half22float2(*(const __half2*)&G[(size_t)c * 64 + lane * 2]);
        ax += v.x; ay += v.y;
    }
}

// ---------------- fused aggregate + next-layer GEMM (4-row batched) -----------
// warp gathers 4 rows, then one epilogue pass reusing each sW read across 4 rows.
template <bool RELU, bool STORE_OUT>
__global__ void __launch_bounds__(512) k_aggf(const __half* __restrict__ G,
                                              const float* __restrict__ bias,
                                              const float* __restrict__ Wn,
                                              float* __restrict__ outp,
                                              __half* __restrict__ Gnext) {
    __shared__ float sW[64 * 64];
    __shared__ float sT[16][4][64];
    for (int idx = threadIdx.x; idx < 64 * 64; idx += 512) sW[idx] = Wn[idx];
    __syncthreads();

    int lane = threadIdx.x & 31;
    int wid  = threadIdx.x >> 5;
    int g0   = blockIdx.x * 16 + wid;
    int ng   = gridDim.x * 16;
    float2 b = *(const float2*)&bias[lane * 2];

    for (int grp = g0; grp * 4 < N_NODES; grp += ng) {
        int base = grp * 4;
        float div[4];
        #pragma unroll
        for (int r = 0; r < 4; r++) {
            int row = base + r;
            float ax, ay;
            gather_row(G, row, lane, ax, ay);
            float di = g_dinv[row];
            div[r] = di;
            float ox = fmaf(ax, di, b.x);
            float oy = fmaf(ay, di, b.y);
            if (RELU) { ox = fmaxf(ox, 0.f); oy = fmaxf(oy, 0.f); }
            if (STORE_OUT)
                *(float2*)&outp[(size_t)row * 64 + lane * 2] = make_float2(ox, oy);
            sT[wid][r][lane * 2]     = ox;
            sT[wid][r][lane * 2 + 1] = oy;
        }
        __syncwarp();
        float gx[4] = {0.f, 0.f, 0.f, 0.f};
        float gy[4] = {0.f, 0.f, 0.f, 0.f};
        #pragma unroll 8
        for (int k = 0; k < 64; k++) {
            float2 w = *(const float2*)&sW[k * 64 + lane * 2];
            #pragma unroll
            for (int r = 0; r < 4; r++) {
                float a = sT[wid][r][k];
                gx[r] = fmaf(a, w.x, gx[r]);
                gy[r] = fmaf(a, w.y, gy[r]);
            }
        }
        #pragma unroll
        for (int r = 0; r < 4; r++) {
            __half2 hv = __floats2half2_rn(gx[r] * div[r], gy[r] * div[r]);
            *(__half2*)&Gnext[(size_t)(base + r) * 64 + lane * 2] = hv;
        }
        __syncwarp();
    }
}

// ---------------- final aggregate: relu + residual, fp32 out ------------------
__global__ void __launch_bounds__(512) k_agg_final(const __half* __restrict__ G,
                                                   const float* __restrict__ bias,
                                                   const float* __restrict__ res,
                                                   float* __restrict__ outp) {
    int lane = threadIdx.x & 31;
    int row0 = (blockIdx.x * 512 + threadIdx.x) >> 5;
    int nw   = (gridDim.x * 512) >> 5;
    float2 b = *(const float2*)&bias[lane * 2];

    for (int row = row0; row < N_NODES; row += nw) {
        float ax, ay;
        gather_row(G, row, lane, ax, ay);
        float di = g_dinv[row];
        float ox = fmaxf(fmaf(ax, di, b.x), 0.f);
        float oy = fmaxf(fmaf(ay, di, b.y), 0.f);
        float2 r = *(const float2*)&res[(size_t)row * 64 + lane * 2];
        *(float2*)&outp[(size_t)row * 64 + lane * 2] = make_float2(ox + r.x, oy + r.y);
    }
}

// ---------------- launch --------------------------------------------------------
extern "C" void kernel_launch(void* const* d_in, const int* in_sizes, int n_in,
                              void* d_out, int out_size) {
    const float* x  = (const float*)d_in[0];
    const void*  ei = d_in[1];
    const float* W0 = (const float*)d_in[2];
    const float* b0 = (const float*)d_in[3];
    const float* Ws = (const float*)d_in[4];
    const float* bs = (const float*)d_in[5];
    float* out = (float*)d_out;

    const float* Ws0 = Ws;
    const float* Ws1 = Ws + 64 * 64;
    const float* bs0 = bs;
    const float* bs1 = bs + 64;

    __half *G = nullptr, *H = nullptr;
    float* XT = nullptr;
    cudaGetSymbolAddress((void**)&G,  g_G);
    cudaGetSymbolAddress((void**)&H,  g_H);
    cudaGetSymbolAddress((void**)&XT, g_XT);

    // ---- CSR build ----
    k_init<<<(N_NODES + 255) / 256, 256>>>(ei);
    k_count<<<(N_EDGES + 511) / 512, 512>>>(ei);
    k_scan1<<<NB_SCAN, 1024>>>();
    k_scan2f<<<NB_SCAN, 1024>>>();
    k_fill<<<(TOT + 511) / 512, 512>>>(ei);

    const int GEMM0_BLOCKS = (N_NODES + 127) / 128;
    const int AGG_BLOCKS   = 592;

    // layer 0: G = dinv*(x@W0);  agg -> XT (fp32);  fused: H = dinv*(XT@Ws0)
    k_gemm0<<<GEMM0_BLOCKS, 256>>>(x, W0, G);
    k_aggf<false, true><<<AGG_BLOCKS, 512>>>(G, b0, Ws0, XT, H);
    // layer 1: agg(relu, not stored); fused: G = dinv*(h1@Ws1)
    k_aggf<true, false><<<AGG_BLOCKS, 512>>>(H, bs0, Ws1, nullptr, G);
    // layer 2: agg(relu) + residual -> out
    k_agg_final<<<AGG_BLOCKS, 512>>>(G, bs1, XT, out);
}

// round 5
// speedup vs baseline: 1.3816x; 1.3816x over previous
#include <cuda_runtime.h>
#include <cuda_bf16.h>

#define N_NODES 100000
#define N_EDGES 1600000
#define TOT (N_EDGES + N_NODES)
#define NB_SCAN ((N_NODES + 1023) / 1024)   // 98

// ---------------- scratch -----------------------------------------------------
__device__ int    g_deg[N_NODES];
__device__ int    g_incl[N_NODES];
__device__ int    g_bsum[128];
__device__ int    g_rowptr[N_NODES + 1];
__device__ int    g_cursor[N_NODES];
__device__ int    g_col[TOT];
__device__ float  g_dinv[N_NODES];
__device__ int    g_is64;

__device__ float g_G[N_NODES * 64];
__device__ float g_H[N_NODES * 64];
__device__ float g_XT[N_NODES * 64];

// ---------------- helpers ------------------------------------------------------
__device__ __forceinline__ int load_idx(const void* ei, int pos) {
    if (g_is64) return (int)((const long long*)ei)[pos];
    return ((const int*)ei)[pos];
}

__global__ void k_init(const void* ei) {
    int i = blockIdx.x * blockDim.x + threadIdx.x;
    if (i < N_NODES) g_deg[i] = 1;
    if (i == 0) {
        const long long* p = (const long long*)ei;
        int ok64 = 1;
        #pragma unroll
        for (int j = 0; j < 16; j++) {
            long long v = p[j];
            if (v < 0 || v >= N_NODES) ok64 = 0;
        }
        g_is64 = ok64;
    }
}

__global__ void k_count(const void* ei) {
    int t = blockIdx.x * blockDim.x + threadIdx.x;
    if (t < N_EDGES) atomicAdd(&g_deg[load_idx(ei, N_EDGES + t)], 1);
}

__global__ void k_scan1() {
    __shared__ int s[1024];
    int tid = threadIdx.x;
    int i = blockIdx.x * 1024 + tid;
    int v = (i < N_NODES) ? g_deg[i] : 0;
    s[tid] = v;
    __syncthreads();
    #pragma unroll
    for (int off = 1; off < 1024; off <<= 1) {
        int t = (tid >= off) ? s[tid - off] : 0;
        __syncthreads();
        s[tid] += t;
        __syncthreads();
    }
    if (i < N_NODES) g_incl[i] = s[tid];
    if (tid == 1023) g_bsum[blockIdx.x] = s[1023];
}

__global__ void k_scan2f() {
    __shared__ int sb[128];
    int tid = threadIdx.x;
    if (tid < 128) sb[tid] = (tid < NB_SCAN) ? g_bsum[tid] : 0;
    __syncthreads();
    int boff = 0;
    for (int j = 0; j < (int)blockIdx.x; j++) boff += sb[j];
    int i = blockIdx.x * 1024 + tid;
    if (i < N_NODES) {
        int rp = g_incl[i] - g_deg[i] + boff;
        g_rowptr[i] = rp;
        g_cursor[i] = rp;
        g_dinv[i]   = rsqrtf((float)g_deg[i]);
    }
    if (i == 0) g_rowptr[N_NODES] = TOT;
}

__global__ void k_fill(const void* ei) {
    int t = blockIdx.x * blockDim.x + threadIdx.x;
    if (t < N_EDGES) {
        int s = load_idx(ei, t);
        int d = load_idx(ei, N_EDGES + t);
        g_col[atomicAdd(&g_cursor[d], 1)] = s;
    } else if (t < TOT) {
        int i = t - N_EDGES;
        g_col[atomicAdd(&g_cursor[i], 1)] = i;
    }
}

// ---------------- tiled GEMM: G = dinv * (X @ W),  X:[N,K]  W:[K,64] ----------
// M-tile 128, 256 threads, 4x8 accum per thread, K-chunks of 32.
template <int K>
__global__ void __launch_bounds__(256) k_gemm(const float* __restrict__ X,
                                              const float* __restrict__ W,
                                              float* __restrict__ G) {
    __shared__ float As[32][132];   // transposed: As[k][row]
    __shared__ float Bs[32][64];
    int tid = threadIdx.x;
    int block_row = blockIdx.x * 128;
    int txc = tid & 7;
    int tyr = tid >> 3;

    int lrow = tid >> 1;
    int kh   = (tid & 1) * 16;
    int lkB  = tid >> 3;
    int lcB  = (tid & 7) * 8;

    float acc[4][8];
    #pragma unroll
    for (int i = 0; i < 4; i++)
        #pragma unroll
        for (int j = 0; j < 8; j++) acc[i][j] = 0.f;

    for (int k0 = 0; k0 < K; k0 += 32) {
        int grow = block_row + lrow;
        #pragma unroll
        for (int j = 0; j < 4; j++) {
            int ko = kh + j * 4;
            float4 v = make_float4(0.f, 0.f, 0.f, 0.f);
            if (grow < N_NODES) v = *(const float4*)&X[(size_t)grow * K + k0 + ko];
            As[ko + 0][lrow] = v.x;
            As[ko + 1][lrow] = v.y;
            As[ko + 2][lrow] = v.z;
            As[ko + 3][lrow] = v.w;
        }
        *(float4*)&Bs[lkB][lcB]     = *(const float4*)&W[(size_t)(k0 + lkB) * 64 + lcB];
        *(float4*)&Bs[lkB][lcB + 4] = *(const float4*)&W[(size_t)(k0 + lkB) * 64 + lcB + 4];
        __syncthreads();

        #pragma unroll 8
        for (int kk = 0; kk < 32; kk++) {
            float4 a  = *(const float4*)&As[kk][tyr * 4];
            float4 b0 = *(const float4*)&Bs[kk][txc * 8];
            float4 b1 = *(const float4*)&Bs[kk][txc * 8 + 4];
            float av[4] = {a.x, a.y, a.z, a.w};
            float bv[8] = {b0.x, b0.y, b0.z, b0.w, b1.x, b1.y, b1.z, b1.w};
            #pragma unroll
            for (int i = 0; i < 4; i++)
                #pragma unroll
                for (int j = 0; j < 8; j++)
                    acc[i][j] = fmaf(av[i], bv[j], acc[i][j]);
        }
        __syncthreads();
    }

    #pragma unroll
    for (int i = 0; i < 4; i++) {
        int gr = block_row + tyr * 4 + i;
        if (gr < N_NODES) {
            float di = g_dinv[gr];
            float4 o0 = make_float4(acc[i][0] * di, acc[i][1] * di, acc[i][2] * di, acc[i][3] * di);
            float4 o1 = make_float4(acc[i][4] * di, acc[i][5] * di, acc[i][6] * di, acc[i][7] * di);
            *(float4*)&G[(size_t)gr * 64 + txc * 8]     = o0;
            *(float4*)&G[(size_t)gr * 64 + txc * 8 + 4] = o1;
        }
    }
}

// ---------------- lean aggregate: out[i] = f(dinv[i]*sum G[col] + b) [+res] ---
// warp-per-node gather, fp32 float2 per lane, unroll 8. No smem.
template <bool RELU, bool ADDRES>
__global__ void __launch_bounds__(512) k_agg(const float* __restrict__ G,
                                             const float* __restrict__ bias,
                                             const float* __restrict__ res,
                                             float* __restrict__ outp) {
    int lane = threadIdx.x & 31;
    int row  = (blockIdx.x * 512 + threadIdx.x) >> 5;
    if (row >= N_NODES) return;

    int s  = g_rowptr[row];
    int en = g_rowptr[row + 1];
    float ax = 0.f, ay = 0.f;
    int e = s;
    for (; e + 8 <= en; e += 8) {
        float2 v[8];
        #pragma unroll
        for (int j = 0; j < 8; j++) {
            int c = g_col[e + j];
            v[j] = *(const float2*)&G[(size_t)c * 64 + lane * 2];
        }
        #pragma unroll
        for (int j = 0; j < 8; j++) { ax += v[j].x; ay += v[j].y; }
    }
    for (; e < en; ++e) {
        int c = g_col[e];
        float2 v = *(const float2*)&G[(size_t)c * 64 + lane * 2];
        ax += v.x; ay += v.y;
    }
    float di = g_dinv[row];
    float2 b = *(const float2*)&bias[lane * 2];
    float ox = fmaf(ax, di, b.x);
    float oy = fmaf(ay, di, b.y);
    if (RELU) { ox = fmaxf(ox, 0.f); oy = fmaxf(oy, 0.f); }
    if (ADDRES) {
        float2 r = *(const float2*)&res[(size_t)row * 64 + lane * 2];
        ox += r.x; oy += r.y;
    }
    *(float2*)&outp[(size_t)row * 64 + lane * 2] = make_float2(ox, oy);
}

// ---------------- launch --------------------------------------------------------
extern "C" void kernel_launch(void* const* d_in, const int* in_sizes, int n_in,
                              void* d_out, int out_size) {
    const float* x  = (const float*)d_in[0];
    const void*  ei = d_in[1];
    const float* W0 = (const float*)d_in[2];
    const float* b0 = (const float*)d_in[3];
    const float* Ws = (const float*)d_in[4];
    const float* bs = (const float*)d_in[5];
    float* out = (float*)d_out;

    const float* Ws0 = Ws;
    const float* Ws1 = Ws + 64 * 64;
    const float* bs0 = bs;
    const float* bs1 = bs + 64;

    float *G = nullptr, *H = nullptr, *XT = nullptr;
    cudaGetSymbolAddress((void**)&G,  g_G);
    cudaGetSymbolAddress((void**)&H,  g_H);
    cudaGetSymbolAddress((void**)&XT, g_XT);

    // ---- CSR build ----
    k_init<<<(N_NODES + 255) / 256, 256>>>(ei);
    k_count<<<(N_EDGES + 511) / 512, 512>>>(ei);
    k_scan1<<<NB_SCAN, 1024>>>();
    k_scan2f<<<NB_SCAN, 1024>>>();
    k_fill<<<(TOT + 511) / 512, 512>>>(ei);

    const int GEMM_BLOCKS = (N_NODES + 127) / 128;           // 782
    const int AGG_BLOCKS  = (N_NODES * 32 + 511) / 512;      // 6250

    // layer 0
    k_gemm<128><<<GEMM_BLOCKS, 256>>>(x, W0, G);             // G  = dinv*(x@W0)
    k_agg<false, false><<<AGG_BLOCKS, 512>>>(G, b0, nullptr, XT);   // XT = agg(G)+b0
    // layer 1
    k_gemm<64><<<GEMM_BLOCKS, 256>>>(XT, Ws0, H);            // H  = dinv*(XT@Ws0)
    k_agg<true, false><<<AGG_BLOCKS, 512>>>(H, bs0, nullptr, G);    // G  = relu(agg(H)+bs0)
    // layer 2
    k_gemm<64><<<GEMM_BLOCKS, 256>>>(G, Ws1, H);             // H  = dinv*(G@Ws1)
    k_agg<true, true><<<AGG_BLOCKS, 512>>>(H, bs1, XT, out); // out= relu(agg+bs1)+XT
}

// round 7
// speedup vs baseline: 1.3957x; 1.0102x over previous
#include <cuda_runtime.h>
#include <cuda_bf16.h>

#define N_NODES 100000
#define N_EDGES 1600000
#define TOT (N_EDGES + N_NODES)
#define NB_SCAN ((N_NODES + 1023) / 1024)   // 98

// ---------------- scratch -----------------------------------------------------
__device__ int    g_deg[N_NODES];
__device__ int    g_incl[N_NODES];
__device__ int    g_bsum[128];
__device__ int    g_rowptr[N_NODES + 1];
__device__ int    g_cursor[N_NODES];
__device__ int    g_col[TOT];            // stores src*64 (premultiplied offset)
__device__ float  g_dinv[N_NODES];
__device__ int    g_is64;

__device__ float g_G[N_NODES * 64];
__device__ float g_H[N_NODES * 64];
__device__ float g_XT[N_NODES * 64];

// ---------------- helpers ------------------------------------------------------
__device__ __forceinline__ int load_idx(const void* ei, int pos) {
    if (g_is64) return (int)((const long long*)ei)[pos];
    return ((const int*)ei)[pos];
}

__global__ void k_init(const void* ei) {
    int i = blockIdx.x * blockDim.x + threadIdx.x;
    if (i < N_NODES) g_deg[i] = 1;
    if (i == 0) {
        const long long* p = (const long long*)ei;
        int ok64 = 1;
        #pragma unroll
        for (int j = 0; j < 16; j++) {
            long long v = p[j];
            if (v < 0 || v >= N_NODES) ok64 = 0;
        }
        g_is64 = ok64;
    }
}

__global__ void k_count(const void* ei) {
    int t = blockIdx.x * blockDim.x + threadIdx.x;
    if (t < N_EDGES) atomicAdd(&g_deg[load_idx(ei, N_EDGES + t)], 1);
}

__global__ void k_scan1() {
    __shared__ int s[1024];
    int tid = threadIdx.x;
    int i = blockIdx.x * 1024 + tid;
    int v = (i < N_NODES) ? g_deg[i] : 0;
    s[tid] = v;
    __syncthreads();
    #pragma unroll
    for (int off = 1; off < 1024; off <<= 1) {
        int t = (tid >= off) ? s[tid - off] : 0;
        __syncthreads();
        s[tid] += t;
        __syncthreads();
    }
    if (i < N_NODES) g_incl[i] = s[tid];
    if (tid == 1023) g_bsum[blockIdx.x] = s[1023];
}

__global__ void k_scan2f() {
    __shared__ int sb[128];
    int tid = threadIdx.x;
    if (tid < 128) sb[tid] = (tid < NB_SCAN) ? g_bsum[tid] : 0;
    __syncthreads();
    int boff = 0;
    for (int j = 0; j < (int)blockIdx.x; j++) boff += sb[j];
    int i = blockIdx.x * 1024 + tid;
    if (i < N_NODES) {
        int rp = g_incl[i] - g_deg[i] + boff;
        g_rowptr[i] = rp;
        g_cursor[i] = rp;
        g_dinv[i]   = rsqrtf((float)g_deg[i]);
    }
    if (i == 0) g_rowptr[N_NODES] = TOT;
}

__global__ void k_fill(const void* ei) {
    int t = blockIdx.x * blockDim.x + threadIdx.x;
    if (t < N_EDGES) {
        int s = load_idx(ei, t);
        int d = load_idx(ei, N_EDGES + t);
        g_col[atomicAdd(&g_cursor[d], 1)] = s * 64;
    } else if (t < TOT) {
        int i = t - N_EDGES;
        g_col[atomicAdd(&g_cursor[i], 1)] = i * 64;
    }
}

// ---------------- tiled GEMM: G = dinv * (X @ W),  X:[N,K]  W:[K,64] ----------
template <int K>
__global__ void __launch_bounds__(256) k_gemm(const float* __restrict__ X,
                                              const float* __restrict__ W,
                                              float* __restrict__ G) {
    __shared__ float As[32][132];
    __shared__ float Bs[32][64];
    int tid = threadIdx.x;
    int block_row = blockIdx.x * 128;
    int txc = tid & 7;
    int tyr = tid >> 3;

    int lrow = tid >> 1;
    int kh   = (tid & 1) * 16;
    int lkB  = tid >> 3;
    int lcB  = (tid & 7) * 8;

    float acc[4][8];
    #pragma unroll
    for (int i = 0; i < 4; i++)
        #pragma unroll
        for (int j = 0; j < 8; j++) acc[i][j] = 0.f;

    for (int k0 = 0; k0 < K; k0 += 32) {
        int grow = block_row + lrow;
        #pragma unroll
        for (int j = 0; j < 4; j++) {
            int ko = kh + j * 4;
            float4 v = make_float4(0.f, 0.f, 0.f, 0.f);
            if (grow < N_NODES) v = *(const float4*)&X[(size_t)grow * K + k0 + ko];
            As[ko + 0][lrow] = v.x;
            As[ko + 1][lrow] = v.y;
            As[ko + 2][lrow] = v.z;
            As[ko + 3][lrow] = v.w;
        }
        *(float4*)&Bs[lkB][lcB]     = *(const float4*)&W[(size_t)(k0 + lkB) * 64 + lcB];
        *(float4*)&Bs[lkB][lcB + 4] = *(const float4*)&W[(size_t)(k0 + lkB) * 64 + lcB + 4];
        __syncthreads();

        #pragma unroll 8
        for (int kk = 0; kk < 32; kk++) {
            float4 a  = *(const float4*)&As[kk][tyr * 4];
            float4 b0 = *(const float4*)&Bs[kk][txc * 8];
            float4 b1 = *(const float4*)&Bs[kk][txc * 8 + 4];
            float av[4] = {a.x, a.y, a.z, a.w};
            float bv[8] = {b0.x, b0.y, b0.z, b0.w, b1.x, b1.y, b1.z, b1.w};
            #pragma unroll
            for (int i = 0; i < 4; i++)
                #pragma unroll
                for (int j = 0; j < 8; j++)
                    acc[i][j] = fmaf(av[i], bv[j], acc[i][j]);
        }
        __syncthreads();
    }

    #pragma unroll
    for (int i = 0; i < 4; i++) {
        int gr = block_row + tyr * 4 + i;
        if (gr < N_NODES) {
            float di = g_dinv[gr];
            float4 o0 = make_float4(acc[i][0] * di, acc[i][1] * di, acc[i][2] * di, acc[i][3] * di);
            float4 o1 = make_float4(acc[i][4] * di, acc[i][5] * di, acc[i][6] * di, acc[i][7] * di);
            *(float4*)&G[(size_t)gr * 64 + txc * 8]     = o0;
            *(float4*)&G[(size_t)gr * 64 + txc * 8 + 4] = o1;
        }
    }
}

// ---------------- paired-edge aggregate ---------------------------------------
// warp-per-node; half-warp per edge (lanes 0-15 edge e, 16-31 edge e+1),
// each lane loads float4 (16 lanes = full 64-ch row). shfl_xor(16) combine.
template <bool RELU, bool ADDRES>
__global__ void __launch_bounds__(512) k_agg(const float* __restrict__ G,
                                             const float* __restrict__ bias,
                                             const float* __restrict__ res,
                                             float* __restrict__ outp) {
    int lane = threadIdx.x & 31;
    int half = lane >> 4;
    int hl4  = (lane & 15) * 4;
    int row  = (blockIdx.x * 512 + threadIdx.x) >> 5;
    if (row >= N_NODES) return;

    int s  = g_rowptr[row];
    int en = g_rowptr[row + 1];
    float ax = 0.f, ay = 0.f, az = 0.f, aw = 0.f;
    int e = s;
    for (; e + 8 <= en; e += 8) {
        float4 v[4];
        #pragma unroll
        for (int j = 0; j < 4; j++) {
            int c64 = g_col[e + 2 * j + half];
            v[j] = *(const float4*)&G[(size_t)(c64 + hl4)];
        }
        #pragma unroll
        for (int j = 0; j < 4; j++) {
            ax += v[j].x; ay += v[j].y; az += v[j].z; aw += v[j].w;
        }
    }
    for (; e + 2 <= en; e += 2) {
        int c64 = g_col[e + half];
        float4 v = *(const float4*)&G[(size_t)(c64 + hl4)];
        ax += v.x; ay += v.y; az += v.z; aw += v.w;
    }
    if (e < en && half == 0) {
        int c64 = g_col[e];
        float4 v = *(const float4*)&G[(size_t)(c64 + hl4)];
        ax += v.x; ay += v.y; az += v.z; aw += v.w;
    }
    // combine half-warps
    ax += __shfl_xor_sync(0xffffffffu, ax, 16);
    ay += __shfl_xor_sync(0xffffffffu, ay, 16);
    az += __shfl_xor_sync(0xffffffffu, az, 16);
    aw += __shfl_xor_sync(0xffffffffu, aw, 16);

    if (half == 0) {
        float di = g_dinv[row];
        float4 b = *(const float4*)&bias[hl4];
        float ox = fmaf(ax, di, b.x);
        float oy = fmaf(ay, di, b.y);
        float oz = fmaf(az, di, b.z);
        float ow = fmaf(aw, di, b.w);
        if (RELU) {
            ox = fmaxf(ox, 0.f); oy = fmaxf(oy, 0.f);
            oz = fmaxf(oz, 0.f); ow = fmaxf(ow, 0.f);
        }
        if (ADDRES) {
            float4 r = *(const float4*)&res[(size_t)row * 64 + hl4];
            ox += r.x; oy += r.y; oz += r.z; ow += r.w;
        }
        *(float4*)&outp[(size_t)row * 64 + hl4] = make_float4(ox, oy, oz, ow);
    }
}

// ---------------- launch --------------------------------------------------------
extern "C" void kernel_launch(void* const* d_in, const int* in_sizes, int n_in,
                              void* d_out, int out_size) {
    const float* x  = (const float*)d_in[0];
    const void*  ei = d_in[1];
    const float* W0 = (const float*)d_in[2];
    const float* b0 = (const float*)d_in[3];
    const float* Ws = (const float*)d_in[4];
    const float* bs = (const float*)d_in[5];
    float* out = (float*)d_out;

    const float* Ws0 = Ws;
    const float* Ws1 = Ws + 64 * 64;
    const float* bs0 = bs;
    const float* bs1 = bs + 64;

    float *G = nullptr, *H = nullptr, *XT = nullptr;
    cudaGetSymbolAddress((void**)&G,  g_G);
    cudaGetSymbolAddress((void**)&H,  g_H);
    cudaGetSymbolAddress((void**)&XT, g_XT);

    // ---- CSR build ----
    k_init<<<(N_NODES + 255) / 256, 256>>>(ei);
    k_count<<<(N_EDGES + 511) / 512, 512>>>(ei);
    k_scan1<<<NB_SCAN, 1024>>>();
    k_scan2f<<<NB_SCAN, 1024>>>();
    k_fill<<<(TOT + 511) / 512, 512>>>(ei);

    const int GEMM_BLOCKS = (N_NODES + 127) / 128;           // 782
    const int AGG_BLOCKS  = (N_NODES * 32 + 511) / 512;      // 6250

    // layer 0
    k_gemm<128><<<GEMM_BLOCKS, 256>>>(x, W0, G);
    k_agg<false, false><<<AGG_BLOCKS, 512>>>(G, b0, nullptr, XT);
    // layer 1
    k_gemm<64><<<GEMM_BLOCKS, 256>>>(XT, Ws0, H);
    k_agg<true, false><<<AGG_BLOCKS, 512>>>(H, bs0, nullptr, G);
    // layer 2
    k_gemm<64><<<GEMM_BLOCKS, 256>>>(G, Ws1, H);
    k_agg<true, true><<<AGG_BLOCKS, 512>>>(H, bs1, XT, out);
}

// round 8
// speedup vs baseline: 1.5508x; 1.1111x over previous
#include <cuda_runtime.h>
#include <cuda_fp16.h>
#include <cuda_bf16.h>

#define N_NODES 100000
#define N_EDGES 1600000
#define TOT (N_EDGES + N_NODES)
#define NB_SCAN ((N_NODES + 1023) / 1024)   // 98

// ---------------- scratch -----------------------------------------------------
__device__ int    g_deg[N_NODES];
__device__ int    g_incl[N_NODES];
__device__ int    g_bsum[128];
__device__ int    g_rowptr[N_NODES + 1];
__device__ int    g_cursor[N_NODES];
__device__ int2   g_cw[TOT];             // {src*64, __float_as_int(dinv[src])}
__device__ float  g_dinv[N_NODES];
__device__ int    g_is64;

__device__ __align__(256) __half g_M[N_NODES * 64];   // fp16 message buffer
__device__ float g_XT[N_NODES * 64];                  // x_temp residual (fp32)
__device__ float g_h1[N_NODES * 64];                  // hidden (fp32)

// ---------------- helpers ------------------------------------------------------
__device__ __forceinline__ int load_idx(const void* ei, int pos) {
    if (g_is64) return (int)((const long long*)ei)[pos];
    return ((const int*)ei)[pos];
}

__global__ void k_init(const void* ei) {
    int i = blockIdx.x * blockDim.x + threadIdx.x;
    if (i < N_NODES) g_deg[i] = 1;
    if (i == 0) {
        const long long* p = (const long long*)ei;
        int ok64 = 1;
        #pragma unroll
        for (int j = 0; j < 16; j++) {
            long long v = p[j];
            if (v < 0 || v >= N_NODES) ok64 = 0;
        }
        g_is64 = ok64;
    }
}

__global__ void k_count(const void* ei) {
    int t = blockIdx.x * blockDim.x + threadIdx.x;
    if (t < N_EDGES) atomicAdd(&g_deg[load_idx(ei, N_EDGES + t)], 1);
}

__global__ void k_scan1() {
    __shared__ int s[1024];
    int tid = threadIdx.x;
    int i = blockIdx.x * 1024 + tid;
    int v = (i < N_NODES) ? g_deg[i] : 0;
    s[tid] = v;
    __syncthreads();
    #pragma unroll
    for (int off = 1; off < 1024; off <<= 1) {
        int t = (tid >= off) ? s[tid - off] : 0;
        __syncthreads();
        s[tid] += t;
        __syncthreads();
    }
    if (i < N_NODES) g_incl[i] = s[tid];
    if (tid == 1023) g_bsum[blockIdx.x] = s[1023];
}

__global__ void k_scan2f() {
    __shared__ int sb[128];
    int tid = threadIdx.x;
    if (tid < 128) sb[tid] = (tid < NB_SCAN) ? g_bsum[tid] : 0;
    __syncthreads();
    int boff = 0;
    for (int j = 0; j < (int)blockIdx.x; j++) boff += sb[j];
    int i = blockIdx.x * 1024 + tid;
    if (i < N_NODES) {
        int rp = g_incl[i] - g_deg[i] + boff;
        g_rowptr[i] = rp;
        g_cursor[i] = rp;
        g_dinv[i]   = rsqrtf((float)g_deg[i]);
    }
    if (i == 0) g_rowptr[N_NODES] = TOT;
}

__global__ void k_fill(const void* ei) {
    int t = blockIdx.x * blockDim.x + threadIdx.x;
    if (t < N_EDGES) {
        int s = load_idx(ei, t);
        int d = load_idx(ei, N_EDGES + t);
        int pos = atomicAdd(&g_cursor[d], 1);
        g_cw[pos] = make_int2(s * 64, __float_as_int(g_dinv[s]));
    } else if (t < TOT) {
        int i = t - N_EDGES;
        int pos = atomicAdd(&g_cursor[i], 1);
        g_cw[pos] = make_int2(i * 64, __float_as_int(g_dinv[i]));
    }
}

// ---------------- tiled GEMM: M16 = [dinv *] (X @ W),  fp16 out ---------------
// M-tile 128, 256 threads, 4x8 accum, K-chunks of 32.
template <int K, bool SCALE>
__global__ void __launch_bounds__(256) k_gemm(const float* __restrict__ X,
                                              const float* __restrict__ W,
                                              __half* __restrict__ M) {
    __shared__ float As[32][132];
    __shared__ float Bs[32][64];
    int tid = threadIdx.x;
    int block_row = blockIdx.x * 128;
    int txc = tid & 7;
    int tyr = tid >> 3;

    int lrow = tid >> 1;
    int kh   = (tid & 1) * 16;
    int lkB  = tid >> 3;
    int lcB  = (tid & 7) * 8;

    float acc[4][8];
    #pragma unroll
    for (int i = 0; i < 4; i++)
        #pragma unroll
        for (int j = 0; j < 8; j++) acc[i][j] = 0.f;

    for (int k0 = 0; k0 < K; k0 += 32) {
        int grow = block_row + lrow;
        #pragma unroll
        for (int j = 0; j < 4; j++) {
            int ko = kh + j * 4;
            float4 v = make_float4(0.f, 0.f, 0.f, 0.f);
            if (grow < N_NODES) v = *(const float4*)&X[(size_t)grow * K + k0 + ko];
            As[ko + 0][lrow] = v.x;
            As[ko + 1][lrow] = v.y;
            As[ko + 2][lrow] = v.z;
            As[ko + 3][lrow] = v.w;
        }
        *(float4*)&Bs[lkB][lcB]     = *(const float4*)&W[(size_t)(k0 + lkB) * 64 + lcB];
        *(float4*)&Bs[lkB][lcB + 4] = *(const float4*)&W[(size_t)(k0 + lkB) * 64 + lcB + 4];
        __syncthreads();

        #pragma unroll 8
        for (int kk = 0; kk < 32; kk++) {
            float4 a  = *(const float4*)&As[kk][tyr * 4];
            float4 b0 = *(const float4*)&Bs[kk][txc * 8];
            float4 b1 = *(const float4*)&Bs[kk][txc * 8 + 4];
            float av[4] = {a.x, a.y, a.z, a.w};
            float bv[8] = {b0.x, b0.y, b0.z, b0.w, b1.x, b1.y, b1.z, b1.w};
            #pragma unroll
            for (int i = 0; i < 4; i++)
                #pragma unroll
                for (int j = 0; j < 8; j++)
                    acc[i][j] = fmaf(av[i], bv[j], acc[i][j]);
        }
        __syncthreads();
    }

    #pragma unroll
    for (int i = 0; i < 4; i++) {
        int gr = block_row + tyr * 4 + i;
        if (gr < N_NODES) {
            float di = SCALE ? g_dinv[gr] : 1.f;
            __half2 h[4];
            #pragma unroll
            for (int j = 0; j < 4; j++)
                h[j] = __floats2half2_rn(acc[i][2 * j] * di, acc[i][2 * j + 1] * di);
            uint4 pack;
            pack.x = *(unsigned*)&h[0];
            pack.y = *(unsigned*)&h[1];
            pack.z = *(unsigned*)&h[2];
            pack.w = *(unsigned*)&h[3];
            *(uint4*)&M[(size_t)gr * 64 + txc * 8] = pack;
        }
    }
}

// ---------------- paired-edge fp16 aggregate ----------------------------------
// warp-per-node; half-warp per edge; lane loads uint2 = 4 halves (its 4 chans).
// WEIGHTED: multiply by per-edge dinv[src] (layer 0, unscaled messages).
template <bool WEIGHTED, bool RELU, bool ADDRES>
__global__ void __launch_bounds__(512) k_agg(const __half* __restrict__ M,
                                             const float* __restrict__ bias,
                                             const float* __restrict__ res,
                                             float* __restrict__ outp) {
    int lane = threadIdx.x & 31;
    int hid  = lane >> 4;
    int hl4  = (lane & 15) * 4;
    int row  = (blockIdx.x * 512 + threadIdx.x) >> 5;
    if (row >= N_NODES) return;

    int s  = g_rowptr[row];
    int en = g_rowptr[row + 1];
    float a0 = 0.f, a1 = 0.f, a2 = 0.f, a3 = 0.f;
    int e = s;
    #pragma unroll 1
    for (; e + 8 <= en; e += 8) {
        #pragma unroll
        for (int j = 0; j < 4; j++) {
            int2 cw = g_cw[e + 2 * j + hid];
            uint2 hv = *(const uint2*)&M[cw.x + hl4];
            float2 lo = __half22float2(*(__half2*)&hv.x);
            float2 hi = __half22float2(*(__half2*)&hv.y);
            if (WEIGHTED) {
                float w = __int_as_float(cw.y);
                a0 = fmaf(lo.x, w, a0); a1 = fmaf(lo.y, w, a1);
                a2 = fmaf(hi.x, w, a2); a3 = fmaf(hi.y, w, a3);
            } else {
                a0 += lo.x; a1 += lo.y; a2 += hi.x; a3 += hi.y;
            }
        }
    }
    for (; e + 2 <= en; e += 2) {
        int2 cw = g_cw[e + hid];
        uint2 hv = *(const uint2*)&M[cw.x + hl4];
        float2 lo = __half22float2(*(__half2*)&hv.x);
        float2 hi = __half22float2(*(__half2*)&hv.y);
        float w = WEIGHTED ? __int_as_float(cw.y) : 1.f;
        a0 = fmaf(lo.x, w, a0); a1 = fmaf(lo.y, w, a1);
        a2 = fmaf(hi.x, w, a2); a3 = fmaf(hi.y, w, a3);
    }
    if (e < en && hid == 0) {
        int2 cw = g_cw[e];
        uint2 hv = *(const uint2*)&M[cw.x + hl4];
        float2 lo = __half22float2(*(__half2*)&hv.x);
        float2 hi = __half22float2(*(__half2*)&hv.y);
        float w = WEIGHTED ? __int_as_float(cw.y) : 1.f;
        a0 = fmaf(lo.x, w, a0); a1 = fmaf(lo.y, w, a1);
        a2 = fmaf(hi.x, w, a2); a3 = fmaf(hi.y, w, a3);
    }
    a0 += __shfl_xor_sync(0xffffffffu, a0, 16);
    a1 += __shfl_xor_sync(0xffffffffu, a1, 16);
    a2 += __shfl_xor_sync(0xffffffffu, a2, 16);
    a3 += __shfl_xor_sync(0xffffffffu, a3, 16);

    if (hid == 0) {
        float di = g_dinv[row];
        float4 b = *(const float4*)&bias[hl4];
        float o0 = fmaf(a0, di, b.x);
        float o1 = fmaf(a1, di, b.y);
        float o2 = fmaf(a2, di, b.z);
        float o3 = fmaf(a3, di, b.w);
        if (RELU) {
            o0 = fmaxf(o0, 0.f); o1 = fmaxf(o1, 0.f);
            o2 = fmaxf(o2, 0.f); o3 = fmaxf(o3, 0.f);
        }
        if (ADDRES) {
            float4 r = *(const float4*)&res[(size_t)row * 64 + hl4];
            o0 += r.x; o1 += r.y; o2 += r.z; o3 += r.w;
        }
        *(float4*)&outp[(size_t)row * 64 + hl4] = make_float4(o0, o1, o2, o3);
    }
}

// ---------------- launch --------------------------------------------------------
extern "C" void kernel_launch(void* const* d_in, const int* in_sizes, int n_in,
                              void* d_out, int out_size) {
    const float* x  = (const float*)d_in[0];
    const void*  ei = d_in[1];
    const float* W0 = (const float*)d_in[2];
    const float* b0 = (const float*)d_in[3];
    const float* Ws = (const float*)d_in[4];
    const float* bs = (const float*)d_in[5];
    float* out = (float*)d_out;

    const float* Ws0 = Ws;
    const float* Ws1 = Ws + 64 * 64;
    const float* bs0 = bs;
    const float* bs1 = bs + 64;

    __half* M = nullptr;
    float *XT = nullptr, *H1 = nullptr;
    cudaGetSymbolAddress((void**)&M,  g_M);
    cudaGetSymbolAddress((void**)&XT, g_XT);
    cudaGetSymbolAddress((void**)&H1, g_h1);

    // persistent side stream + events (created on first, non-captured call)
    static cudaStream_t s2 = nullptr;
    static cudaEvent_t evF = nullptr, evG = nullptr;
    if (s2 == nullptr) {
        cudaStreamCreateWithFlags(&s2, cudaStreamNonBlocking);
        cudaEventCreateWithFlags(&evF, cudaEventDisableTiming);
        cudaEventCreateWithFlags(&evG, cudaEventDisableTiming);
    }

    const int GEMM_BLOCKS = (N_NODES + 127) / 128;           // 782
    const int AGG_BLOCKS  = (N_NODES * 32 + 511) / 512;      // 6250

    // ---- fork: gemm0 (independent of graph build) on side stream ----
    cudaEventRecord(evF, 0);
    cudaStreamWaitEvent(s2, evF, 0);
    k_gemm<128, false><<<GEMM_BLOCKS, 256, 0, s2>>>(x, W0, M);  // M = fp16(x@W0)
    cudaEventRecord(evG, s2);

    // ---- CSR build on default stream (concurrent with gemm0) ----
    k_init<<<(N_NODES + 255) / 256, 256>>>(ei);
    k_count<<<(N_EDGES + 511) / 512, 512>>>(ei);
    k_scan1<<<NB_SCAN, 1024>>>();
    k_scan2f<<<NB_SCAN, 1024>>>();
    k_fill<<<(TOT + 511) / 512, 512>>>(ei);

    // ---- join, then the serial conv chain ----
    cudaStreamWaitEvent(0, evG, 0);
    // layer 0: XT = agg_w(M) + b0   (per-edge dinv[src] weights)
    k_agg<true, false, false><<<AGG_BLOCKS, 512>>>(M, b0, nullptr, XT);
    // layer 1: M = fp16(dinv*(XT@Ws0)); h1 = relu(agg(M)+bs0)
    k_gemm<64, true><<<GEMM_BLOCKS, 256>>>(XT, Ws0, M);
    k_agg<false, true, false><<<AGG_BLOCKS, 512>>>(M, bs0, nullptr, H1);
    // layer 2: M = fp16(dinv*(h1@Ws1)); out = relu(agg(M)+bs1) + XT
    k_gemm<64, true><<<GEMM_BLOCKS, 256>>>(H1, Ws1, M);
    k_agg<false, true, true><<<AGG_BLOCKS, 512>>>(M, bs1, XT, out);
}